// round 11
// baseline (speedup 1.0000x reference)
#include <cuda_runtime.h>
#include <cuda_bf16.h>
#include <cstdint>

#define BB    8
#define SS    2048
#define DIN   2048
#define DOUT  2048
#define KK    16
#define RR    16

// Pre-split bf16 hi/lo mixed weights (u32 = packed bf16 pair over last dim),
// plus K-split z partials.
__device__ __align__(16) uint32_t g_Amh[BB * RR * DIN / 2];    // [b][r][i/2]
__device__ __align__(16) uint32_t g_Aml[BB * RR * DIN / 2];
__device__ __align__(16) uint32_t g_BmTh[BB * DOUT * RR / 2];  // [b][o][r/2]
__device__ __align__(16) uint32_t g_BmTl[BB * DOUT * RR / 2];
__device__ __align__(16) float    g_zp[2 * BB * SS * RR];      // [kh][b][s][r]

// ---------------------------------------------------------------------------
__device__ __forceinline__ void split2(float x, float y, uint32_t &hi, uint32_t &lo) {
    __nv_bfloat162 h2 = __floats2bfloat162_rn(x, y);
    float rx = x - __bfloat162float(h2.x);
    float ry = y - __bfloat162float(h2.y);
    __nv_bfloat162 l2 = __floats2bfloat162_rn(rx, ry);
    hi = *reinterpret_cast<uint32_t*>(&h2);
    lo = *reinterpret_cast<uint32_t*>(&l2);
}

__device__ __forceinline__ void pack4(float4 v, uint2 &hi, uint2 &lo) {
    split2(v.x, v.y, hi.x, lo.x);
    split2(v.z, v.w, hi.y, lo.y);
}

// m16n8k16 bf16 mma, fp32 accumulate.
__device__ __forceinline__ void mma16(float* d,
                                      uint32_t a0, uint32_t a1, uint32_t a2, uint32_t a3,
                                      uint32_t b0, uint32_t b1) {
    asm("mma.sync.aligned.m16n8k16.row.col.f32.bf16.bf16.f32 "
        "{%0,%1,%2,%3}, {%4,%5,%6,%7}, {%8,%9}, {%0,%1,%2,%3};"
        : "+f"(d[0]), "+f"(d[1]), "+f"(d[2]), "+f"(d[3])
        : "r"(a0), "r"(a1), "r"(a2), "r"(a3), "r"(b0), "r"(b1));
}

// ---------------------------------------------------------------------------
// Kernel 1: mix banks -> pre-split bf16 hi/lo. Each thread covers 2 batches.
// B-part lane mapping now fully coalesced: 4 consecutive lanes cover one o's
// r-quads -> warp reads 512B contiguous per k.
// ---------------------------------------------------------------------------
__global__ void __launch_bounds__(256, 2) mix_kernel(const float* __restrict__ alpha,
                                                     const float* __restrict__ Abank,
                                                     const float* __restrict__ Bbank) {
    __shared__ float sal[BB * KK];
    if (threadIdx.x < BB * KK) sal[threadIdx.x] = alpha[threadIdx.x];
    __syncthreads();

    int t = blockIdx.x * blockDim.x + threadIdx.x;
    if (t < 32768) {
        int bg  = t >> 13;
        int rem = t & 8191;
        int r   = rem >> 9;
        int i   = (rem & 511) << 2;
        const float* ab = Abank + (size_t)r * DIN + i;
        float4 a0 = make_float4(0.f, 0.f, 0.f, 0.f);
        float4 a1 = a0;
#pragma unroll
        for (int k = 0; k < KK; k++) {
            float4 v = *(const float4*)(ab + (size_t)k * RR * DIN);
            float c0 = sal[(2 * bg) * KK + k];
            float c1 = sal[(2 * bg + 1) * KK + k];
            a0.x += c0 * v.x; a0.y += c0 * v.y; a0.z += c0 * v.z; a0.w += c0 * v.w;
            a1.x += c1 * v.x; a1.y += c1 * v.y; a1.z += c1 * v.z; a1.w += c1 * v.w;
        }
        uint2 hi, lo;
        size_t idx0 = (size_t)((2 * bg) * RR + r) * (DIN / 2) + (i >> 1);
        pack4(a0, hi, lo);
        *(uint2*)&g_Amh[idx0] = hi;  *(uint2*)&g_Aml[idx0] = lo;
        size_t idx1 = (size_t)((2 * bg + 1) * RR + r) * (DIN / 2) + (i >> 1);
        pack4(a1, hi, lo);
        *(uint2*)&g_Amh[idx1] = hi;  *(uint2*)&g_Aml[idx1] = lo;
    } else {
        // B: bg(4) x o(2048) x q(4); q = lane&3 -> coalesced 512B per warp.
        int t2  = t - 32768;
        int bg  = t2 >> 13;
        int rem = t2 & 8191;
        int o   = rem >> 2;
        int q   = rem & 3;
        const float* bb = Bbank + (size_t)o * RR + 4 * q;
        float4 a0 = make_float4(0.f, 0.f, 0.f, 0.f);
        float4 a1 = a0;
#pragma unroll
        for (int k = 0; k < KK; k++) {
            float4 v = *(const float4*)(bb + (size_t)k * DOUT * RR);
            float c0 = sal[(2 * bg) * KK + k];
            float c1 = sal[(2 * bg + 1) * KK + k];
            a0.x += c0 * v.x; a0.y += c0 * v.y; a0.z += c0 * v.z; a0.w += c0 * v.w;
            a1.x += c1 * v.x; a1.y += c1 * v.y; a1.z += c1 * v.z; a1.w += c1 * v.w;
        }
        uint2 hi, lo;
        size_t idx0 = (size_t)((2 * bg) * DOUT + o) * (RR / 2) + 2 * q;
        pack4(a0, hi, lo);
        *(uint2*)&g_BmTh[idx0] = hi;  *(uint2*)&g_BmTl[idx0] = lo;
        size_t idx1 = (size_t)((2 * bg + 1) * DOUT + o) * (RR / 2) + 2 * q;
        pack4(a1, hi, lo);
        *(uint2*)&g_BmTh[idx1] = hi;  *(uint2*)&g_BmTl[idx1] = lo;
    }
}

// ---------------------------------------------------------------------------
// Kernel 2: z partials, transposed m16n8k16 mma: A = Am (M=16 r), B = h (N=s).
//   g_zp[kh][b][s][r] = sum_{i in half} Am[b,r,i] * h[b,s,i]
// Grid 512 = kh(2) x st(32, 64 s) x b(8); 256 thr = 8 warps x 8 s. OCC 4
// (24.6 KB smem) -> 4 CTAs/SM cross-hide the per-chunk DRAM latency.
// Per 64-i chunk per warp: 4 k16 steps x (12 LDS + 3 mma).
// ---------------------------------------------------------------------------
__global__ void __launch_bounds__(256, 4) z_mma_kernel(const float* __restrict__ h) {
    __shared__ uint32_t hs_hi[64 * 36];
    __shared__ uint32_t hs_lo[64 * 36];
    __shared__ uint32_t as_hi[32 * 24];
    __shared__ uint32_t as_lo[32 * 24];

    int kh = blockIdx.x & 1;
    int st = (blockIdx.x >> 1) & 31;
    int b  = blockIdx.x >> 6;
    int s0 = st * 64;
    int ibase = kh * (DIN / 4);   // u32 columns per K-half = 512

    int tid  = threadIdx.x;
    int w    = tid >> 5;
    int lane = tid & 31;
    int gid  = lane >> 2;
    int tig  = lane & 3;

    int row16 = tid >> 4;         // staging rows per pass
    int col   = tid & 15;         // float4 column

    const uint32_t* amh = g_Amh + (size_t)b * RR * (DIN / 2);
    const uint32_t* aml = g_Aml + (size_t)b * RR * (DIN / 2);

    float d[4] = {0.f, 0.f, 0.f, 0.f};

#pragma unroll 1
    for (int c = 0; c < 16; c++) {
        int icol0 = ibase + c * 32;

        // ---- load h sub-tile (64 s x 64 i) to regs, coalesced ----
        float4 v[4];
#pragma unroll
        for (int p = 0; p < 4; p++)
            v[p] = *(const float4*)(h + (size_t)(b * SS + s0 + p * 16 + row16) * DIN
                                      + 2 * icol0 + col * 4);
        // ---- load Am chunk (16 r x 32 u32-cols) to regs ----
        uint32_t ar_hi[2], ar_lo[2];
        {
            int rr = tid & 15;
            int ic = tid >> 4;
#pragma unroll
            for (int p = 0; p < 2; p++) {
                size_t gidx = (size_t)rr * (DIN / 2) + icol0 + ic + p * 16;
                ar_hi[p] = amh[gidx];
                ar_lo[p] = aml[gidx];
            }
        }

        __syncthreads();   // previous chunk fully consumed

        // ---- stage (split h once here) ----
#pragma unroll
        for (int p = 0; p < 4; p++) {
            uint32_t h01, l01, h23, l23;
            split2(v[p].x, v[p].y, h01, l01);
            split2(v[p].z, v[p].w, h23, l23);
            int base = (p * 16 + row16) * 36 + col * 2;
            hs_hi[base]     = h01;  hs_hi[base + 1] = h23;
            hs_lo[base]     = l01;  hs_lo[base + 1] = l23;
        }
        {
            int rr = tid & 15;
            int ic = tid >> 4;
#pragma unroll
            for (int p = 0; p < 2; p++) {
                as_hi[(ic + p * 16) * 24 + rr] = ar_hi[p];
                as_lo[(ic + p * 16) * 24 + rr] = ar_lo[p];
            }
        }
        __syncthreads();

        // ---- compute: 4 k16 steps ----
#pragma unroll
        for (int km = 0; km < 4; km++) {
            int ac0 = (km * 8 + tig) * 24;
            int ac1 = (km * 8 + 4 + tig) * 24;
            uint32_t Ah0 = as_hi[ac0 + gid], Ah1 = as_hi[ac0 + gid + 8];
            uint32_t Ah2 = as_hi[ac1 + gid], Ah3 = as_hi[ac1 + gid + 8];
            uint32_t Al0 = as_lo[ac0 + gid], Al1 = as_lo[ac0 + gid + 8];
            uint32_t Al2 = as_lo[ac1 + gid], Al3 = as_lo[ac1 + gid + 8];

            int srow = (w * 8 + gid) * 36 + km * 8 + tig;
            uint32_t Bh0 = hs_hi[srow], Bh1 = hs_hi[srow + 4];
            uint32_t Bl0 = hs_lo[srow], Bl1 = hs_lo[srow + 4];
            mma16(d, Ah0, Ah1, Ah2, Ah3, Bh0, Bh1);
            mma16(d, Ah0, Ah1, Ah2, Ah3, Bl0, Bl1);
            mma16(d, Al0, Al1, Al2, Al3, Bh0, Bh1);
        }
    }

    // Epilogue: D rows = r (gid, gid+8), cols = s (2tig, 2tig+1).
    float* zp = g_zp + ((size_t)(kh * BB + b) * SS) * RR;
    int sbase = s0 + w * 8 + 2 * tig;
    zp[(size_t)sbase * RR + gid]           = d[0];
    zp[(size_t)(sbase + 1) * RR + gid]     = d[1];
    zp[(size_t)sbase * RR + gid + 8]       = d[2];
    zp[(size_t)(sbase + 1) * RR + gid + 8] = d[3];
}

// ---------------------------------------------------------------------------
// Kernel 3: delta[b][s][o] = sum_r z[b][s][r] * BmT[b][o][r]
// m16n8k16: 3 mma per 16x8 tile. Unchanged from R10. 2048 CTAs, 512 thr.
// ---------------------------------------------------------------------------
__global__ void __launch_bounds__(512, 2) delta_kernel(float* __restrict__ out) {
    __shared__ float zs[128 * 20];
    __shared__ uint32_t bsh[128 * 9];
    __shared__ uint32_t bsl[128 * 9];

    int ot = blockIdx.x & 15;
    int st = (blockIdx.x >> 4) & 15;
    int b  = blockIdx.x >> 8;
    int s0 = st * 128;
    int o0 = ot * 128;
    int tid = threadIdx.x;

    {
        int row = tid >> 2;
        int col = (tid & 3) << 2;
        size_t src = ((size_t)(b * SS) + s0 + row) * RR + col;
        float4 p0 = *(const float4*)(g_zp + src);
        float4 p1 = *(const float4*)(g_zp + (size_t)BB * SS * RR + src);
        *(float4*)(zs + row * 20 + col) =
            make_float4(p0.x + p1.x, p0.y + p1.y, p0.z + p1.z, p0.w + p1.w);
    }
    {
        size_t base = (size_t)(b * DOUT + o0) * (RR / 2);
#pragma unroll
        for (int j = 0; j < 2; j++) {
            int idx = tid * 2 + j;
            int row = idx >> 3;
            int col = idx & 7;
            bsh[row * 9 + col] = g_BmTh[base + idx];
            bsl[row * 9 + col] = g_BmTl[base + idx];
        }
    }
    __syncthreads();

    int w = tid >> 5;
    int lane = tid & 31;
    int gid = lane >> 2;
    int tig = lane & 3;
    int sw = (w & 7) * 16;
    int ow = (w >> 3) * 64;

    uint32_t Ah[4], Al[4];
#pragma unroll
    for (int kk = 0; kk < 2; kk++) {
        float2 v0 = *(const float2*)(zs + (sw + gid) * 20 + kk * 8 + tig * 2);
        float2 v1 = *(const float2*)(zs + (sw + gid + 8) * 20 + kk * 8 + tig * 2);
        split2(v0.x, v0.y, Ah[2 * kk],     Al[2 * kk]);
        split2(v1.x, v1.y, Ah[2 * kk + 1], Al[2 * kk + 1]);
    }

#pragma unroll
    for (int nt = 0; nt < 8; nt++) {
        int brow = (ow + nt * 8 + gid) * 9;
        uint32_t Bh0 = bsh[brow + tig];
        uint32_t Bh1 = bsh[brow + 4 + tig];
        uint32_t Bl0 = bsl[brow + tig];
        uint32_t Bl1 = bsl[brow + 4 + tig];

        float d[4] = {0.f, 0.f, 0.f, 0.f};
        mma16(d, Ah[0], Ah[1], Ah[2], Ah[3], Bh0, Bh1);
        mma16(d, Ah[0], Ah[1], Ah[2], Ah[3], Bl0, Bl1);
        mma16(d, Al[0], Al[1], Al[2], Al[3], Bh0, Bh1);

        float* op = out + ((size_t)(b * SS + s0 + sw + gid)) * DOUT
                        + o0 + ow + nt * 8 + tig * 2;
        *(float2*)op = make_float2(d[0], d[1]);
        *(float2*)(op + (size_t)8 * DOUT) = make_float2(d[2], d[3]);
    }
}

// ---------------------------------------------------------------------------
extern "C" void kernel_launch(void* const* d_in, const int* in_sizes, int n_in,
                              void* d_out, int out_size) {
    const float* h     = (const float*)d_in[0];   // [8,2048,2048]
    const float* alpha = (const float*)d_in[1];   // [8,16]
    const float* Abank = (const float*)d_in[2];   // [16,16,2048]
    const float* Bbank = (const float*)d_in[3];   // [16,2048,16]
    float* out = (float*)d_out;                   // [8,2048,2048]

    mix_kernel<<<256, 256>>>(alpha, Abank, Bbank);
    z_mma_kernel<<<512, 256>>>(h);
    delta_kernel<<<2048, 512>>>(out);
}

// round 12
// speedup vs baseline: 1.1779x; 1.1779x over previous
#include <cuda_runtime.h>
#include <cuda_bf16.h>
#include <cstdint>

#define BB    8
#define SS    2048
#define DIN   2048
#define DOUT  2048
#define KK    16
#define RR    16

// Pre-split bf16 hi/lo mixed weights (u32 = packed bf16 pair over last dim),
// plus K-split z partials.
__device__ __align__(16) uint32_t g_Amh[BB * RR * DIN / 2];    // [b][r][i/2]
__device__ __align__(16) uint32_t g_Aml[BB * RR * DIN / 2];
__device__ __align__(16) uint32_t g_BmTh[BB * DOUT * RR / 2];  // [b][o][r/2]
__device__ __align__(16) uint32_t g_BmTl[BB * DOUT * RR / 2];
__device__ __align__(16) float    g_zp[2 * BB * SS * RR];      // [kh][b][s][r]

// ---------------------------------------------------------------------------
__device__ __forceinline__ void split2(float x, float y, uint32_t &hi, uint32_t &lo) {
    __nv_bfloat162 h2 = __floats2bfloat162_rn(x, y);
    float rx = x - __bfloat162float(h2.x);
    float ry = y - __bfloat162float(h2.y);
    __nv_bfloat162 l2 = __floats2bfloat162_rn(rx, ry);
    hi = *reinterpret_cast<uint32_t*>(&h2);
    lo = *reinterpret_cast<uint32_t*>(&l2);
}

__device__ __forceinline__ void pack4(float4 v, uint2 &hi, uint2 &lo) {
    split2(v.x, v.y, hi.x, lo.x);
    split2(v.z, v.w, hi.y, lo.y);
}

// m16n8k16 bf16 mma, fp32 accumulate.
__device__ __forceinline__ void mma16(float* d,
                                      uint32_t a0, uint32_t a1, uint32_t a2, uint32_t a3,
                                      uint32_t b0, uint32_t b1) {
    asm("mma.sync.aligned.m16n8k16.row.col.f32.bf16.bf16.f32 "
        "{%0,%1,%2,%3}, {%4,%5,%6,%7}, {%8,%9}, {%0,%1,%2,%3};"
        : "+f"(d[0]), "+f"(d[1]), "+f"(d[2]), "+f"(d[3])
        : "r"(a0), "r"(a1), "r"(a2), "r"(a3), "r"(b0), "r"(b1));
}

// ---------------------------------------------------------------------------
// Kernel 1: mix banks -> pre-split bf16 hi/lo (R11 version: B-part coalesced).
// ---------------------------------------------------------------------------
__global__ void __launch_bounds__(256, 2) mix_kernel(const float* __restrict__ alpha,
                                                     const float* __restrict__ Abank,
                                                     const float* __restrict__ Bbank) {
    __shared__ float sal[BB * KK];
    if (threadIdx.x < BB * KK) sal[threadIdx.x] = alpha[threadIdx.x];
    __syncthreads();

    int t = blockIdx.x * blockDim.x + threadIdx.x;
    if (t < 32768) {
        int bg  = t >> 13;
        int rem = t & 8191;
        int r   = rem >> 9;
        int i   = (rem & 511) << 2;
        const float* ab = Abank + (size_t)r * DIN + i;
        float4 a0 = make_float4(0.f, 0.f, 0.f, 0.f);
        float4 a1 = a0;
#pragma unroll
        for (int k = 0; k < KK; k++) {
            float4 v = *(const float4*)(ab + (size_t)k * RR * DIN);
            float c0 = sal[(2 * bg) * KK + k];
            float c1 = sal[(2 * bg + 1) * KK + k];
            a0.x += c0 * v.x; a0.y += c0 * v.y; a0.z += c0 * v.z; a0.w += c0 * v.w;
            a1.x += c1 * v.x; a1.y += c1 * v.y; a1.z += c1 * v.z; a1.w += c1 * v.w;
        }
        uint2 hi, lo;
        size_t idx0 = (size_t)((2 * bg) * RR + r) * (DIN / 2) + (i >> 1);
        pack4(a0, hi, lo);
        *(uint2*)&g_Amh[idx0] = hi;  *(uint2*)&g_Aml[idx0] = lo;
        size_t idx1 = (size_t)((2 * bg + 1) * RR + r) * (DIN / 2) + (i >> 1);
        pack4(a1, hi, lo);
        *(uint2*)&g_Amh[idx1] = hi;  *(uint2*)&g_Aml[idx1] = lo;
    } else {
        // B: bg(4) x o(2048) x q(4); q = lane&3 -> coalesced 512B per warp.
        int t2  = t - 32768;
        int bg  = t2 >> 13;
        int rem = t2 & 8191;
        int o   = rem >> 2;
        int q   = rem & 3;
        const float* bb = Bbank + (size_t)o * RR + 4 * q;
        float4 a0 = make_float4(0.f, 0.f, 0.f, 0.f);
        float4 a1 = a0;
#pragma unroll
        for (int k = 0; k < KK; k++) {
            float4 v = *(const float4*)(bb + (size_t)k * DOUT * RR);
            float c0 = sal[(2 * bg) * KK + k];
            float c1 = sal[(2 * bg + 1) * KK + k];
            a0.x += c0 * v.x; a0.y += c0 * v.y; a0.z += c0 * v.z; a0.w += c0 * v.w;
            a1.x += c1 * v.x; a1.y += c1 * v.y; a1.z += c1 * v.z; a1.w += c1 * v.w;
        }
        uint2 hi, lo;
        size_t idx0 = (size_t)((2 * bg) * DOUT + o) * (RR / 2) + 2 * q;
        pack4(a0, hi, lo);
        *(uint2*)&g_BmTh[idx0] = hi;  *(uint2*)&g_BmTl[idx0] = lo;
        size_t idx1 = (size_t)((2 * bg + 1) * DOUT + o) * (RR / 2) + 2 * q;
        pack4(a1, hi, lo);
        *(uint2*)&g_BmTh[idx1] = hi;  *(uint2*)&g_BmTl[idx1] = lo;
    }
}

// ---------------------------------------------------------------------------
// Kernel 2: z partials, transposed m16n8k16 mma, SOFTWARE-PIPELINED.
//   g_zp[kh][b][s][r] = sum_{i in half} Am[b,r,i] * h[b,s,i]
// Grid 256 = kh(2) x st(16, 128 s) x b(8); 256 thr = 8 warps x 16 s.
// Pipeline: prefetch chunk c+1's LDGs right after staging chunk c, BEFORE
// compute c -> DRAM latency hidden behind ~1.5K cyc of mma/LDS per chunk.
// ---------------------------------------------------------------------------
__global__ void __launch_bounds__(256, 2) z_mma_kernel(const float* __restrict__ h) {
    __shared__ uint32_t hs_hi[128 * 36];
    __shared__ uint32_t hs_lo[128 * 36];
    __shared__ uint32_t as_hi[32 * 24];
    __shared__ uint32_t as_lo[32 * 24];

    int kh = blockIdx.x & 1;
    int st = (blockIdx.x >> 1) & 15;
    int b  = blockIdx.x >> 5;
    int s0 = st * 128;
    int ibase = kh * (DIN / 4);   // u32 columns per K-half = 512

    int tid  = threadIdx.x;
    int w    = tid >> 5;
    int lane = tid & 31;
    int gid  = lane >> 2;
    int tig  = lane & 3;

    int row16 = tid >> 4;
    int col   = tid & 15;

    const uint32_t* amh = g_Amh + (size_t)b * RR * (DIN / 2);
    const uint32_t* aml = g_Aml + (size_t)b * RR * (DIN / 2);
    const float*    hb  = h + (size_t)(b * SS + s0 + row16) * DIN + col * 4;

    int arr = tid & 15;        // Am gather: r
    int aic = tid >> 4;        // Am gather: col 0..15 (+16)

    float d[2][4];
#pragma unroll
    for (int nt = 0; nt < 2; nt++)
#pragma unroll
        for (int j = 0; j < 4; j++) d[nt][j] = 0.f;

    // ---- preload chunk 0 ----
    float4 v[8];
    uint32_t ar_hi[2], ar_lo[2];
    {
        int icol0 = ibase;
#pragma unroll
        for (int p = 0; p < 8; p++)
            v[p] = *(const float4*)(hb + (size_t)(p * 16) * DIN + 2 * icol0);
#pragma unroll
        for (int p = 0; p < 2; p++) {
            size_t gidx = (size_t)arr * (DIN / 2) + icol0 + aic + p * 16;
            ar_hi[p] = amh[gidx];
            ar_lo[p] = aml[gidx];
        }
    }

#pragma unroll 1
    for (int c = 0; c < 16; c++) {
        __syncthreads();   // previous chunk fully consumed

        // ---- stage current chunk (split h once here) ----
#pragma unroll
        for (int p = 0; p < 8; p++) {
            uint32_t h01, l01, h23, l23;
            split2(v[p].x, v[p].y, h01, l01);
            split2(v[p].z, v[p].w, h23, l23);
            int base = (p * 16 + row16) * 36 + col * 2;
            hs_hi[base]     = h01;  hs_hi[base + 1] = h23;
            hs_lo[base]     = l01;  hs_lo[base + 1] = l23;
        }
#pragma unroll
        for (int p = 0; p < 2; p++) {
            as_hi[(aic + p * 16) * 24 + arr] = ar_hi[p];
            as_lo[(aic + p * 16) * 24 + arr] = ar_lo[p];
        }
        __syncthreads();

        // ---- prefetch next chunk (regs dead after staging; LDG in flight
        //      overlaps the compute below) ----
        if (c < 15) {
            int icoln = ibase + (c + 1) * 32;
#pragma unroll
            for (int p = 0; p < 8; p++)
                v[p] = *(const float4*)(hb + (size_t)(p * 16) * DIN + 2 * icoln);
#pragma unroll
            for (int p = 0; p < 2; p++) {
                size_t gidx = (size_t)arr * (DIN / 2) + icoln + aic + p * 16;
                ar_hi[p] = amh[gidx];
                ar_lo[p] = aml[gidx];
            }
        }

        // ---- compute current chunk: 4 k16 steps ----
#pragma unroll
        for (int km = 0; km < 4; km++) {
            int ac0 = (km * 8 + tig) * 24;
            int ac1 = (km * 8 + 4 + tig) * 24;
            uint32_t Ah0 = as_hi[ac0 + gid], Ah1 = as_hi[ac0 + gid + 8];
            uint32_t Ah2 = as_hi[ac1 + gid], Ah3 = as_hi[ac1 + gid + 8];
            uint32_t Al0 = as_lo[ac0 + gid], Al1 = as_lo[ac0 + gid + 8];
            uint32_t Al2 = as_lo[ac1 + gid], Al3 = as_lo[ac1 + gid + 8];
#pragma unroll
            for (int nt = 0; nt < 2; nt++) {
                int srow = (w * 16 + nt * 8 + gid) * 36 + km * 8 + tig;
                uint32_t Bh0 = hs_hi[srow], Bh1 = hs_hi[srow + 4];
                uint32_t Bl0 = hs_lo[srow], Bl1 = hs_lo[srow + 4];
                mma16(d[nt], Ah0, Ah1, Ah2, Ah3, Bh0, Bh1);
                mma16(d[nt], Ah0, Ah1, Ah2, Ah3, Bl0, Bl1);
                mma16(d[nt], Al0, Al1, Al2, Al3, Bh0, Bh1);
            }
        }
    }

    // Epilogue: D rows = r (gid, gid+8), cols = s (2tig, 2tig+1).
    float* zp = g_zp + ((size_t)(kh * BB + b) * SS) * RR;
#pragma unroll
    for (int nt = 0; nt < 2; nt++) {
        int sbase = s0 + w * 16 + nt * 8 + 2 * tig;
        zp[(size_t)sbase * RR + gid]           = d[nt][0];
        zp[(size_t)(sbase + 1) * RR + gid]     = d[nt][1];
        zp[(size_t)sbase * RR + gid + 8]       = d[nt][2];
        zp[(size_t)(sbase + 1) * RR + gid + 8] = d[nt][3];
    }
}

// ---------------------------------------------------------------------------
// Kernel 3: delta[b][s][o] = sum_r z[b][s][r] * BmT[b][o][r]
// m16n8k16: 3 mma per 16x8 tile. Unchanged (proven). 2048 CTAs, 512 thr.
// ---------------------------------------------------------------------------
__global__ void __launch_bounds__(512, 2) delta_kernel(float* __restrict__ out) {
    __shared__ float zs[128 * 20];
    __shared__ uint32_t bsh[128 * 9];
    __shared__ uint32_t bsl[128 * 9];

    int ot = blockIdx.x & 15;
    int st = (blockIdx.x >> 4) & 15;
    int b  = blockIdx.x >> 8;
    int s0 = st * 128;
    int o0 = ot * 128;
    int tid = threadIdx.x;

    {
        int row = tid >> 2;
        int col = (tid & 3) << 2;
        size_t src = ((size_t)(b * SS) + s0 + row) * RR + col;
        float4 p0 = *(const float4*)(g_zp + src);
        float4 p1 = *(const float4*)(g_zp + (size_t)BB * SS * RR + src);
        *(float4*)(zs + row * 20 + col) =
            make_float4(p0.x + p1.x, p0.y + p1.y, p0.z + p1.z, p0.w + p1.w);
    }
    {
        size_t base = (size_t)(b * DOUT + o0) * (RR / 2);
#pragma unroll
        for (int j = 0; j < 2; j++) {
            int idx = tid * 2 + j;
            int row = idx >> 3;
            int col = idx & 7;
            bsh[row * 9 + col] = g_BmTh[base + idx];
            bsl[row * 9 + col] = g_BmTl[base + idx];
        }
    }
    __syncthreads();

    int w = tid >> 5;
    int lane = tid & 31;
    int gid = lane >> 2;
    int tig = lane & 3;
    int sw = (w & 7) * 16;
    int ow = (w >> 3) * 64;

    uint32_t Ah[4], Al[4];
#pragma unroll
    for (int kk = 0; kk < 2; kk++) {
        float2 v0 = *(const float2*)(zs + (sw + gid) * 20 + kk * 8 + tig * 2);
        float2 v1 = *(const float2*)(zs + (sw + gid + 8) * 20 + kk * 8 + tig * 2);
        split2(v0.x, v0.y, Ah[2 * kk],     Al[2 * kk]);
        split2(v1.x, v1.y, Ah[2 * kk + 1], Al[2 * kk + 1]);
    }

#pragma unroll
    for (int nt = 0; nt < 8; nt++) {
        int brow = (ow + nt * 8 + gid) * 9;
        uint32_t Bh0 = bsh[brow + tig];
        uint32_t Bh1 = bsh[brow + 4 + tig];
        uint32_t Bl0 = bsl[brow + tig];
        uint32_t Bl1 = bsl[brow + 4 + tig];

        float d[4] = {0.f, 0.f, 0.f, 0.f};
        mma16(d, Ah[0], Ah[1], Ah[2], Ah[3], Bh0, Bh1);
        mma16(d, Ah[0], Ah[1], Ah[2], Ah[3], Bl0, Bl1);
        mma16(d, Al[0], Al[1], Al[2], Al[3], Bh0, Bh1);

        float* op = out + ((size_t)(b * SS + s0 + sw + gid)) * DOUT
                        + o0 + ow + nt * 8 + tig * 2;
        *(float2*)op = make_float2(d[0], d[1]);
        *(float2*)(op + (size_t)8 * DOUT) = make_float2(d[2], d[3]);
    }
}

// ---------------------------------------------------------------------------
extern "C" void kernel_launch(void* const* d_in, const int* in_sizes, int n_in,
                              void* d_out, int out_size) {
    const float* h     = (const float*)d_in[0];   // [8,2048,2048]
    const float* alpha = (const float*)d_in[1];   // [8,16]
    const float* Abank = (const float*)d_in[2];   // [16,16,2048]
    const float* Bbank = (const float*)d_in[3];   // [16,2048,16]
    float* out = (float*)d_out;                   // [8,2048,2048]

    mix_kernel<<<256, 256>>>(alpha, Abank, Bbank);
    z_mma_kernel<<<256, 256>>>(h);
    delta_kernel<<<2048, 512>>>(out);
}

// round 13
// speedup vs baseline: 1.1932x; 1.0130x over previous
#include <cuda_runtime.h>
#include <cuda_bf16.h>
#include <cstdint>

#define BB    8
#define SS    2048
#define DIN   2048
#define DOUT  2048
#define KK    16
#define RR    16

// Pre-split bf16 hi/lo mixed weights (u32 = packed bf16 pair over last dim),
// plus K-split z partials.
__device__ __align__(16) uint32_t g_Amh[BB * RR * DIN / 2];    // [b][r][i/2]
__device__ __align__(16) uint32_t g_Aml[BB * RR * DIN / 2];
__device__ __align__(16) uint32_t g_BmTh[BB * DOUT * RR / 2];  // [b][o][r/2]
__device__ __align__(16) uint32_t g_BmTl[BB * DOUT * RR / 2];
__device__ __align__(16) float    g_zp[2 * BB * SS * RR];      // [kh][b][s][r]

// z smem buffer layout (u32 words): hs_hi[4608] hs_lo[4608] as_hi[768] as_lo[768]
#define ZB_HSLO 4608
#define ZB_ASHI 9216
#define ZB_ASLO 9984
#define ZB_SIZE 10752            // words per buffer
#define Z_SMEM_BYTES (2 * ZB_SIZE * 4)   // 86016

// ---------------------------------------------------------------------------
__device__ __forceinline__ void split2(float x, float y, uint32_t &hi, uint32_t &lo) {
    __nv_bfloat162 h2 = __floats2bfloat162_rn(x, y);
    float rx = x - __bfloat162float(h2.x);
    float ry = y - __bfloat162float(h2.y);
    __nv_bfloat162 l2 = __floats2bfloat162_rn(rx, ry);
    hi = *reinterpret_cast<uint32_t*>(&h2);
    lo = *reinterpret_cast<uint32_t*>(&l2);
}

__device__ __forceinline__ void pack4(float4 v, uint2 &hi, uint2 &lo) {
    split2(v.x, v.y, hi.x, lo.x);
    split2(v.z, v.w, hi.y, lo.y);
}

// m16n8k16 bf16 mma, fp32 accumulate.
__device__ __forceinline__ void mma16(float* d,
                                      uint32_t a0, uint32_t a1, uint32_t a2, uint32_t a3,
                                      uint32_t b0, uint32_t b1) {
    asm("mma.sync.aligned.m16n8k16.row.col.f32.bf16.bf16.f32 "
        "{%0,%1,%2,%3}, {%4,%5,%6,%7}, {%8,%9}, {%0,%1,%2,%3};"
        : "+f"(d[0]), "+f"(d[1]), "+f"(d[2]), "+f"(d[3])
        : "r"(a0), "r"(a1), "r"(a2), "r"(a3), "r"(b0), "r"(b1));
}

// ---------------------------------------------------------------------------
// Kernel 1: mix banks -> pre-split bf16 hi/lo (coalesced B part). Unchanged.
// ---------------------------------------------------------------------------
__global__ void __launch_bounds__(256, 2) mix_kernel(const float* __restrict__ alpha,
                                                     const float* __restrict__ Abank,
                                                     const float* __restrict__ Bbank) {
    __shared__ float sal[BB * KK];
    if (threadIdx.x < BB * KK) sal[threadIdx.x] = alpha[threadIdx.x];
    __syncthreads();

    int t = blockIdx.x * blockDim.x + threadIdx.x;
    if (t < 32768) {
        int bg  = t >> 13;
        int rem = t & 8191;
        int r   = rem >> 9;
        int i   = (rem & 511) << 2;
        const float* ab = Abank + (size_t)r * DIN + i;
        float4 a0 = make_float4(0.f, 0.f, 0.f, 0.f);
        float4 a1 = a0;
#pragma unroll
        for (int k = 0; k < KK; k++) {
            float4 v = *(const float4*)(ab + (size_t)k * RR * DIN);
            float c0 = sal[(2 * bg) * KK + k];
            float c1 = sal[(2 * bg + 1) * KK + k];
            a0.x += c0 * v.x; a0.y += c0 * v.y; a0.z += c0 * v.z; a0.w += c0 * v.w;
            a1.x += c1 * v.x; a1.y += c1 * v.y; a1.z += c1 * v.z; a1.w += c1 * v.w;
        }
        uint2 hi, lo;
        size_t idx0 = (size_t)((2 * bg) * RR + r) * (DIN / 2) + (i >> 1);
        pack4(a0, hi, lo);
        *(uint2*)&g_Amh[idx0] = hi;  *(uint2*)&g_Aml[idx0] = lo;
        size_t idx1 = (size_t)((2 * bg + 1) * RR + r) * (DIN / 2) + (i >> 1);
        pack4(a1, hi, lo);
        *(uint2*)&g_Amh[idx1] = hi;  *(uint2*)&g_Aml[idx1] = lo;
    } else {
        int t2  = t - 32768;
        int bg  = t2 >> 13;
        int rem = t2 & 8191;
        int o   = rem >> 2;
        int q   = rem & 3;
        const float* bb = Bbank + (size_t)o * RR + 4 * q;
        float4 a0 = make_float4(0.f, 0.f, 0.f, 0.f);
        float4 a1 = a0;
#pragma unroll
        for (int k = 0; k < KK; k++) {
            float4 v = *(const float4*)(bb + (size_t)k * DOUT * RR);
            float c0 = sal[(2 * bg) * KK + k];
            float c1 = sal[(2 * bg + 1) * KK + k];
            a0.x += c0 * v.x; a0.y += c0 * v.y; a0.z += c0 * v.z; a0.w += c0 * v.w;
            a1.x += c1 * v.x; a1.y += c1 * v.y; a1.z += c1 * v.z; a1.w += c1 * v.w;
        }
        uint2 hi, lo;
        size_t idx0 = (size_t)((2 * bg) * DOUT + o) * (RR / 2) + 2 * q;
        pack4(a0, hi, lo);
        *(uint2*)&g_BmTh[idx0] = hi;  *(uint2*)&g_BmTl[idx0] = lo;
        size_t idx1 = (size_t)((2 * bg + 1) * DOUT + o) * (RR / 2) + 2 * q;
        pack4(a1, hi, lo);
        *(uint2*)&g_BmTh[idx1] = hi;  *(uint2*)&g_BmTl[idx1] = lo;
    }
}

// ---------------------------------------------------------------------------
// Kernel 2: z partials, DOUBLE-BUFFERED pipeline.
//   g_zp[kh][b][s][r] = sum_{i in half} Am[b,r,i] * h[b,s,i]
// Grid 256 = kh(2) x st(16, 128 s) x b(8); 256 thr = 8 warps x 16 s.
// Per chunk: stage(c+1 -> other buf) + prefetch(c+2 -> regs) + compute(c),
// ONE __syncthreads. Staging hides under the ~3K-cyc compute window.
// ---------------------------------------------------------------------------
__global__ void __launch_bounds__(256, 2) z_mma_kernel(const float* __restrict__ h) {
    extern __shared__ uint32_t zsm[];
    uint32_t* const buf0 = zsm;
    uint32_t* const buf1 = zsm + ZB_SIZE;

    int kh = blockIdx.x & 1;
    int st = (blockIdx.x >> 1) & 15;
    int b  = blockIdx.x >> 5;
    int s0 = st * 128;
    int ibase = kh * (DIN / 4);   // u32 columns per K-half = 512

    int tid  = threadIdx.x;
    int w    = tid >> 5;
    int lane = tid & 31;
    int gid  = lane >> 2;
    int tig  = lane & 3;

    int row16 = tid >> 4;
    int col   = tid & 15;

    const uint32_t* amh = g_Amh + (size_t)b * RR * (DIN / 2);
    const uint32_t* aml = g_Aml + (size_t)b * RR * (DIN / 2);
    const float*    hb  = h + (size_t)(b * SS + s0 + row16) * DIN + col * 4;

    int arr = tid & 15;        // Am gather: r
    int aic = tid >> 4;        // Am gather: col 0..15 (+16)

    float d[2][4];
#pragma unroll
    for (int nt = 0; nt < 2; nt++)
#pragma unroll
        for (int j = 0; j < 4; j++) d[nt][j] = 0.f;

    float4 v[8];
    uint32_t ar_hi[2], ar_lo[2];

    // ---- load chunk 0 regs ----
    {
        int icol0 = ibase;
#pragma unroll
        for (int p = 0; p < 8; p++)
            v[p] = *(const float4*)(hb + (size_t)(p * 16) * DIN + 2 * icol0);
#pragma unroll
        for (int p = 0; p < 2; p++) {
            size_t gidx = (size_t)arr * (DIN / 2) + icol0 + aic + p * 16;
            ar_hi[p] = amh[gidx];
            ar_lo[p] = aml[gidx];
        }
    }
    // ---- stage chunk 0 -> buf0 ----
    {
        uint32_t* hsh = buf0;
        uint32_t* hsl = buf0 + ZB_HSLO;
#pragma unroll
        for (int p = 0; p < 8; p++) {
            uint32_t h01, l01, h23, l23;
            split2(v[p].x, v[p].y, h01, l01);
            split2(v[p].z, v[p].w, h23, l23);
            int base = (p * 16 + row16) * 36 + col * 2;
            hsh[base] = h01;  hsh[base + 1] = h23;
            hsl[base] = l01;  hsl[base + 1] = l23;
        }
        uint32_t* ash = buf0 + ZB_ASHI;
        uint32_t* asl = buf0 + ZB_ASLO;
#pragma unroll
        for (int p = 0; p < 2; p++) {
            ash[(aic + p * 16) * 24 + arr] = ar_hi[p];
            asl[(aic + p * 16) * 24 + arr] = ar_lo[p];
        }
    }
    __syncthreads();

    // ---- prefetch chunk 1 regs ----
    {
        int icol1 = ibase + 32;
#pragma unroll
        for (int p = 0; p < 8; p++)
            v[p] = *(const float4*)(hb + (size_t)(p * 16) * DIN + 2 * icol1);
#pragma unroll
        for (int p = 0; p < 2; p++) {
            size_t gidx = (size_t)arr * (DIN / 2) + icol1 + aic + p * 16;
            ar_hi[p] = amh[gidx];
            ar_lo[p] = aml[gidx];
        }
    }

#pragma unroll 1
    for (int c = 0; c < 16; c++) {
        uint32_t* cur = (c & 1) ? buf1 : buf0;
        uint32_t* nxt = (c & 1) ? buf0 : buf1;

        // ---- stage chunk c+1 into nxt (regs already loaded) ----
        if (c < 15) {
            uint32_t* hsh = nxt;
            uint32_t* hsl = nxt + ZB_HSLO;
#pragma unroll
            for (int p = 0; p < 8; p++) {
                uint32_t h01, l01, h23, l23;
                split2(v[p].x, v[p].y, h01, l01);
                split2(v[p].z, v[p].w, h23, l23);
                int base = (p * 16 + row16) * 36 + col * 2;
                hsh[base] = h01;  hsh[base + 1] = h23;
                hsl[base] = l01;  hsl[base + 1] = l23;
            }
            uint32_t* ash = nxt + ZB_ASHI;
            uint32_t* asl = nxt + ZB_ASLO;
#pragma unroll
            for (int p = 0; p < 2; p++) {
                ash[(aic + p * 16) * 24 + arr] = ar_hi[p];
                asl[(aic + p * 16) * 24 + arr] = ar_lo[p];
            }
        }

        // ---- prefetch chunk c+2 regs (v dead after staging) ----
        if (c < 14) {
            int icoln = ibase + (c + 2) * 32;
#pragma unroll
            for (int p = 0; p < 8; p++)
                v[p] = *(const float4*)(hb + (size_t)(p * 16) * DIN + 2 * icoln);
#pragma unroll
            for (int p = 0; p < 2; p++) {
                size_t gidx = (size_t)arr * (DIN / 2) + icoln + aic + p * 16;
                ar_hi[p] = amh[gidx];
                ar_lo[p] = aml[gidx];
            }
        }

        // ---- compute chunk c from cur: 4 k16 steps ----
        {
            const uint32_t* hsh = cur;
            const uint32_t* hsl = cur + ZB_HSLO;
            const uint32_t* ash = cur + ZB_ASHI;
            const uint32_t* asl = cur + ZB_ASLO;
#pragma unroll
            for (int km = 0; km < 4; km++) {
                int ac0 = (km * 8 + tig) * 24;
                int ac1 = (km * 8 + 4 + tig) * 24;
                uint32_t Ah0 = ash[ac0 + gid], Ah1 = ash[ac0 + gid + 8];
                uint32_t Ah2 = ash[ac1 + gid], Ah3 = ash[ac1 + gid + 8];
                uint32_t Al0 = asl[ac0 + gid], Al1 = asl[ac0 + gid + 8];
                uint32_t Al2 = asl[ac1 + gid], Al3 = asl[ac1 + gid + 8];
#pragma unroll
                for (int nt = 0; nt < 2; nt++) {
                    int srow = (w * 16 + nt * 8 + gid) * 36 + km * 8 + tig;
                    uint32_t Bh0 = hsh[srow], Bh1 = hsh[srow + 4];
                    uint32_t Bl0 = hsl[srow], Bl1 = hsl[srow + 4];
                    mma16(d[nt], Ah0, Ah1, Ah2, Ah3, Bh0, Bh1);
                    mma16(d[nt], Ah0, Ah1, Ah2, Ah3, Bl0, Bl1);
                    mma16(d[nt], Al0, Al1, Al2, Al3, Bh0, Bh1);
                }
            }
        }
        __syncthreads();   // nxt fully staged; cur free for re-staging
    }

    // Epilogue: D rows = r (gid, gid+8), cols = s (2tig, 2tig+1).
    float* zp = g_zp + ((size_t)(kh * BB + b) * SS) * RR;
#pragma unroll
    for (int nt = 0; nt < 2; nt++) {
        int sbase = s0 + w * 16 + nt * 8 + 2 * tig;
        zp[(size_t)sbase * RR + gid]           = d[nt][0];
        zp[(size_t)(sbase + 1) * RR + gid]     = d[nt][1];
        zp[(size_t)sbase * RR + gid + 8]       = d[nt][2];
        zp[(size_t)(sbase + 1) * RR + gid + 8] = d[nt][3];
    }
}

// ---------------------------------------------------------------------------
// Kernel 3: delta[b][s][o] = sum_r z[b][s][r] * BmT[b][o][r]
// m16n8k16: 3 mma per 16x8 tile. Unchanged (at its floor). 2048 CTAs, 512 thr.
// ---------------------------------------------------------------------------
__global__ void __launch_bounds__(512, 2) delta_kernel(float* __restrict__ out) {
    __shared__ float zs[128 * 20];
    __shared__ uint32_t bsh[128 * 9];
    __shared__ uint32_t bsl[128 * 9];

    int ot = blockIdx.x & 15;
    int st = (blockIdx.x >> 4) & 15;
    int b  = blockIdx.x >> 8;
    int s0 = st * 128;
    int o0 = ot * 128;
    int tid = threadIdx.x;

    {
        int row = tid >> 2;
        int col = (tid & 3) << 2;
        size_t src = ((size_t)(b * SS) + s0 + row) * RR + col;
        float4 p0 = *(const float4*)(g_zp + src);
        float4 p1 = *(const float4*)(g_zp + (size_t)BB * SS * RR + src);
        *(float4*)(zs + row * 20 + col) =
            make_float4(p0.x + p1.x, p0.y + p1.y, p0.z + p1.z, p0.w + p1.w);
    }
    {
        size_t base = (size_t)(b * DOUT + o0) * (RR / 2);
#pragma unroll
        for (int j = 0; j < 2; j++) {
            int idx = tid * 2 + j;
            int row = idx >> 3;
            int col = idx & 7;
            bsh[row * 9 + col] = g_BmTh[base + idx];
            bsl[row * 9 + col] = g_BmTl[base + idx];
        }
    }
    __syncthreads();

    int w = tid >> 5;
    int lane = tid & 31;
    int gid = lane >> 2;
    int tig = lane & 3;
    int sw = (w & 7) * 16;
    int ow = (w >> 3) * 64;

    uint32_t Ah[4], Al[4];
#pragma unroll
    for (int kk = 0; kk < 2; kk++) {
        float2 v0 = *(const float2*)(zs + (sw + gid) * 20 + kk * 8 + tig * 2);
        float2 v1 = *(const float2*)(zs + (sw + gid + 8) * 20 + kk * 8 + tig * 2);
        split2(v0.x, v0.y, Ah[2 * kk],     Al[2 * kk]);
        split2(v1.x, v1.y, Ah[2 * kk + 1], Al[2 * kk + 1]);
    }

#pragma unroll
    for (int nt = 0; nt < 8; nt++) {
        int brow = (ow + nt * 8 + gid) * 9;
        uint32_t Bh0 = bsh[brow + tig];
        uint32_t Bh1 = bsh[brow + 4 + tig];
        uint32_t Bl0 = bsl[brow + tig];
        uint32_t Bl1 = bsl[brow + 4 + tig];

        float d[4] = {0.f, 0.f, 0.f, 0.f};
        mma16(d, Ah[0], Ah[1], Ah[2], Ah[3], Bh0, Bh1);
        mma16(d, Ah[0], Ah[1], Ah[2], Ah[3], Bl0, Bl1);
        mma16(d, Al[0], Al[1], Al[2], Al[3], Bh0, Bh1);

        float* op = out + ((size_t)(b * SS + s0 + sw + gid)) * DOUT
                        + o0 + ow + nt * 8 + tig * 2;
        *(float2*)op = make_float2(d[0], d[1]);
        *(float2*)(op + (size_t)8 * DOUT) = make_float2(d[2], d[3]);
    }
}

// ---------------------------------------------------------------------------
extern "C" void kernel_launch(void* const* d_in, const int* in_sizes, int n_in,
                              void* d_out, int out_size) {
    const float* h     = (const float*)d_in[0];   // [8,2048,2048]
    const float* alpha = (const float*)d_in[1];   // [8,16]
    const float* Abank = (const float*)d_in[2];   // [16,16,2048]
    const float* Bbank = (const float*)d_in[3];   // [16,2048,16]
    float* out = (float*)d_out;                   // [8,2048,2048]

    static bool attr_set = false;
    if (!attr_set) {
        cudaFuncSetAttribute(z_mma_kernel,
                             cudaFuncAttributeMaxDynamicSharedMemorySize,
                             Z_SMEM_BYTES);
        attr_set = true;
    }

    mix_kernel<<<256, 256>>>(alpha, Abank, Bbank);
    z_mma_kernel<<<256, 256, Z_SMEM_BYTES>>>(h);
    delta_kernel<<<2048, 512>>>(out);
}